// round 2
// baseline (speedup 1.0000x reference)
#include <cuda_runtime.h>
#include <cuda_bf16.h>

#define HID 64
#define NB  32
#define TPB 128
#define EPW 128              // edges per warp (32 lanes x 4 edges)
#define EPB 512              // edges per block (4 warps)

typedef unsigned long long ull;

// ---- packed fp32x2 helpers ----
__device__ __forceinline__ ull dup2(float a) {
    ull r; asm("mov.b64 %0,{%1,%1};" : "=l"(r) : "f"(a)); return r;
}
__device__ __forceinline__ void up2(ull v, float& a, float& b) {
    asm("mov.b64 {%0,%1},%2;" : "=f"(a), "=f"(b) : "l"(v));
}
__device__ __forceinline__ void fma2(ull& d, ull a, ull b) {
    asm("fma.rn.f32x2 %0,%1,%2,%0;" : "+l"(d) : "l"(a), "l"(b));
}
__device__ __forceinline__ void red4(float* p, float a, float b, float c, float d) {
    asm volatile("red.global.add.v4.f32 [%0],{%1,%2,%3,%4};"
                 :: "l"(p), "f"(a), "f"(b), "f"(c), "f"(d) : "memory");
}
__device__ __forceinline__ float silu_f(float y) {
    return __fdividef(y, 1.f + __expf(-y));
}

// shared layout (float indices)
#define OFF_W1 0                         // 32*64 (current m)
#define OFF_W2 2048                      // 64*64
#define OFF_B1 6144                      // 64
#define OFF_B2 6208                      // 64
#define OFF_X  6272                      // 4 warps * 32 * 128   [w][k][e]
#define OFF_H  (OFF_X + 4 * NB * EPW)    // 4 warps * 64 * 128   [w][j][e]
#define SMEM_FLOATS (OFF_H + 4 * HID * EPW)
#define SMEM_BYTES  (SMEM_FLOATS * 4)

__global__ void __launch_bounds__(TPB, 1) tpc_edge_kernel(
    const float* __restrict__ scalar, const float* __restrict__ vec,
    const float* __restrict__ elen,   const int* __restrict__ eidx,
    const float* __restrict__ sw1, const float* __restrict__ sb1,
    const float* __restrict__ sw2, const float* __restrict__ sb2,
    const float* __restrict__ vw1, const float* __restrict__ vb1,
    const float* __restrict__ vw2, const float* __restrict__ vb2,
    float* __restrict__ out, int E, long long nscal)
{
    extern __shared__ float sm[];
    int tid  = threadIdx.x;
    int lane = tid & 31;
    int wrp  = tid >> 5;

    long long eq = (long long)blockIdx.x * EPB + (long long)wrp * EPW + lane * 4;

    float* xw = sm + OFF_X + wrp * (NB * EPW);
    float* hw = sm + OFF_H + wrp * (HID * EPW);

    // ---- stage x transposed [k][edge] (warp/thread-private region) ----
    int rows[4], cols[4]; bool val[4];
    #pragma unroll
    for (int i = 0; i < 4; i++) {
        long long e = eq + i;
        val[i] = (e < E);
        long long ec = val[i] ? e : 0;
        rows[i] = eidx[ec];
        cols[i] = eidx[E + ec];
        const float4* xr = (const float4*)(elen + ec * NB);
        #pragma unroll
        for (int c = 0; c < NB / 4; c++) {
            float4 v = xr[c];
            xw[(4 * c + 0) * EPW + lane * 4 + i] = v.x;
            xw[(4 * c + 1) * EPW + lane * 4 + i] = v.y;
            xw[(4 * c + 2) * EPW + lane * 4 + i] = v.z;
            xw[(4 * c + 3) * EPW + lane * 4 + i] = v.w;
        }
    }

    #pragma unroll 1
    for (int m = 0; m < 2; m++) {
        // ---- cooperative weight load for this m ----
        __syncthreads();
        {
            const float4* g1 = (const float4*)(m ? vw1 : sw1);
            const float4* g2 = (const float4*)(m ? vw2 : sw2);
            float4* d1 = (float4*)(sm + OFF_W1);
            float4* d2 = (float4*)(sm + OFF_W2);
            #pragma unroll
            for (int i = 0; i < (NB * HID / 4) / TPB; i++)         // 4
                d1[i * TPB + tid] = g1[i * TPB + tid];
            #pragma unroll
            for (int i = 0; i < (HID * HID / 4) / TPB; i++)        // 8
                d2[i * TPB + tid] = g2[i * TPB + tid];
            if (tid < HID) {
                sm[OFF_B1 + tid] = (m ? vb1 : sb1)[tid];
                sm[OFF_B2 + tid] = (m ? vb2 : sb2)[tid];
            }
        }
        __syncthreads();

        // ---- layer 1: h = silu(x @ w1 + b1), 4 j-tiles of 16 ----
        #pragma unroll 1
        for (int jt = 0; jt < 4; jt++) {
            int j0 = jt * 16;
            ull acc[32];
            {
                const ull* bp = (const ull*)(sm + OFF_B1 + j0);
                #pragma unroll
                for (int q = 0; q < 8; q++) {
                    ull b = bp[q];
                    acc[q] = b; acc[8 + q] = b; acc[16 + q] = b; acc[24 + q] = b;
                }
            }
            #pragma unroll 4
            for (int k = 0; k < NB; k++) {
                float4 xv = *(const float4*)(xw + k * EPW + lane * 4);
                const ulonglong2* wp = (const ulonglong2*)(sm + OFF_W1 + k * HID + j0);
                ulonglong2 wa = wp[0], wb = wp[1], wc = wp[2], wd = wp[3];
                ull x0 = dup2(xv.x), x1 = dup2(xv.y), x2 = dup2(xv.z), x3 = dup2(xv.w);
                fma2(acc[0], x0, wa.x); fma2(acc[1], x0, wa.y);
                fma2(acc[2], x0, wb.x); fma2(acc[3], x0, wb.y);
                fma2(acc[4], x0, wc.x); fma2(acc[5], x0, wc.y);
                fma2(acc[6], x0, wd.x); fma2(acc[7], x0, wd.y);
                fma2(acc[8],  x1, wa.x); fma2(acc[9],  x1, wa.y);
                fma2(acc[10], x1, wb.x); fma2(acc[11], x1, wb.y);
                fma2(acc[12], x1, wc.x); fma2(acc[13], x1, wc.y);
                fma2(acc[14], x1, wd.x); fma2(acc[15], x1, wd.y);
                fma2(acc[16], x2, wa.x); fma2(acc[17], x2, wa.y);
                fma2(acc[18], x2, wb.x); fma2(acc[19], x2, wb.y);
                fma2(acc[20], x2, wc.x); fma2(acc[21], x2, wc.y);
                fma2(acc[22], x2, wd.x); fma2(acc[23], x2, wd.y);
                fma2(acc[24], x3, wa.x); fma2(acc[25], x3, wa.y);
                fma2(acc[26], x3, wb.x); fma2(acc[27], x3, wb.y);
                fma2(acc[28], x3, wc.x); fma2(acc[29], x3, wc.y);
                fma2(acc[30], x3, wd.x); fma2(acc[31], x3, wd.y);
            }
            // silu + transpose-store h[j][edge-quad]
            #pragma unroll
            for (int q = 0; q < 8; q++) {
                float a0, b0, a1, b1, a2, b2, a3, b3;
                up2(acc[q],      a0, b0);
                up2(acc[8 + q],  a1, b1);
                up2(acc[16 + q], a2, b2);
                up2(acc[24 + q], a3, b3);
                float4 lo = make_float4(silu_f(a0), silu_f(a1), silu_f(a2), silu_f(a3));
                float4 hi = make_float4(silu_f(b0), silu_f(b1), silu_f(b2), silu_f(b3));
                *(float4*)(hw + (j0 + 2 * q)     * EPW + lane * 4) = lo;
                *(float4*)(hw + (j0 + 2 * q + 1) * EPW + lane * 4) = hi;
            }
        }

        // ---- layer 2 + gather + scatter, 4 j-tiles of 16 ----
        #pragma unroll 1
        for (int jt = 0; jt < 4; jt++) {
            int j0 = jt * 16;
            ull acc[32];
            {
                const ull* bp = (const ull*)(sm + OFF_B2 + j0);
                #pragma unroll
                for (int q = 0; q < 8; q++) {
                    ull b = bp[q];
                    acc[q] = b; acc[8 + q] = b; acc[16 + q] = b; acc[24 + q] = b;
                }
            }
            #pragma unroll 4
            for (int k = 0; k < HID; k++) {
                float4 hv = *(const float4*)(hw + k * EPW + lane * 4);
                const ulonglong2* wp = (const ulonglong2*)(sm + OFF_W2 + k * HID + j0);
                ulonglong2 wa = wp[0], wb = wp[1], wc = wp[2], wd = wp[3];
                ull h0 = dup2(hv.x), h1 = dup2(hv.y), h2 = dup2(hv.z), h3 = dup2(hv.w);
                fma2(acc[0], h0, wa.x); fma2(acc[1], h0, wa.y);
                fma2(acc[2], h0, wb.x); fma2(acc[3], h0, wb.y);
                fma2(acc[4], h0, wc.x); fma2(acc[5], h0, wc.y);
                fma2(acc[6], h0, wd.x); fma2(acc[7], h0, wd.y);
                fma2(acc[8],  h1, wa.x); fma2(acc[9],  h1, wa.y);
                fma2(acc[10], h1, wb.x); fma2(acc[11], h1, wb.y);
                fma2(acc[12], h1, wc.x); fma2(acc[13], h1, wc.y);
                fma2(acc[14], h1, wd.x); fma2(acc[15], h1, wd.y);
                fma2(acc[16], h2, wa.x); fma2(acc[17], h2, wa.y);
                fma2(acc[18], h2, wb.x); fma2(acc[19], h2, wb.y);
                fma2(acc[20], h2, wc.x); fma2(acc[21], h2, wc.y);
                fma2(acc[22], h2, wd.x); fma2(acc[23], h2, wd.y);
                fma2(acc[24], h3, wa.x); fma2(acc[25], h3, wa.y);
                fma2(acc[26], h3, wb.x); fma2(acc[27], h3, wb.y);
                fma2(acc[28], h3, wc.x); fma2(acc[29], h3, wc.y);
                fma2(acc[30], h3, wd.x); fma2(acc[31], h3, wd.y);
            }

            if (m == 0) {
                #pragma unroll
                for (int e = 0; e < 4; e++) {
                    if (!val[e]) continue;
                    const float4* g = (const float4*)(scalar + (size_t)cols[e] * HID + j0);
                    float4 g0 = g[0], g1 = g[1], g2 = g[2], g3 = g[3];
                    float we[16];
                    #pragma unroll
                    for (int q = 0; q < 8; q++) up2(acc[e * 8 + q], we[2 * q], we[2 * q + 1]);
                    float* dp = out + (size_t)rows[e] * HID + j0;
                    red4(dp + 0,  g0.x * we[0],  g0.y * we[1],  g0.z * we[2],  g0.w * we[3]);
                    red4(dp + 4,  g1.x * we[4],  g1.y * we[5],  g1.z * we[6],  g1.w * we[7]);
                    red4(dp + 8,  g2.x * we[8],  g2.y * we[9],  g2.z * we[10], g2.w * we[11]);
                    red4(dp + 12, g3.x * we[12], g3.y * we[13], g3.z * we[14], g3.w * we[15]);
                }
            } else {
                #pragma unroll
                for (int e = 0; e < 4; e++) {
                    if (!val[e]) continue;
                    float we[16];
                    #pragma unroll
                    for (int q = 0; q < 8; q++) up2(acc[e * 8 + q], we[2 * q], we[2 * q + 1]);
                    #pragma unroll
                    for (int d = 0; d < 3; d++) {
                        const float4* g = (const float4*)(vec + (size_t)cols[e] * 3 * HID + d * HID + j0);
                        float4 g0 = g[0], g1 = g[1], g2 = g[2], g3 = g[3];
                        float* dp = out + nscal + (size_t)rows[e] * 3 * HID + d * HID + j0;
                        red4(dp + 0,  g0.x * we[0],  g0.y * we[1],  g0.z * we[2],  g0.w * we[3]);
                        red4(dp + 4,  g1.x * we[4],  g1.y * we[5],  g1.z * we[6],  g1.w * we[7]);
                        red4(dp + 8,  g2.x * we[8],  g2.y * we[9],  g2.z * we[10], g2.w * we[11]);
                        red4(dp + 12, g3.x * we[12], g3.y * we[13], g3.z * we[14], g3.w * we[15]);
                    }
                }
            }
        }
    }
}

extern "C" void kernel_launch(void* const* d_in, const int* in_sizes, int n_in,
                              void* d_out, int out_size)
{
    const float* scalar = (const float*)d_in[0];
    const float* vec    = (const float*)d_in[1];
    // d_in[2] = edge_sh (unused)
    const float* elen   = (const float*)d_in[3];
    const int*   eidx   = (const int*)d_in[4];
    const float* sw1 = (const float*)d_in[5];
    const float* sb1 = (const float*)d_in[6];
    const float* sw2 = (const float*)d_in[7];
    const float* sb2 = (const float*)d_in[8];
    const float* vw1 = (const float*)d_in[9];
    const float* vb1 = (const float*)d_in[10];
    const float* vw2 = (const float*)d_in[11];
    const float* vb2 = (const float*)d_in[12];

    int E  = in_sizes[3] / NB;              // 500000
    int Nn = in_sizes[0] / HID;             // 50000
    long long nscal = (long long)Nn * HID;

    cudaMemsetAsync(d_out, 0, (size_t)out_size * sizeof(float));

    cudaFuncSetAttribute(tpc_edge_kernel,
                         cudaFuncAttributeMaxDynamicSharedMemorySize, SMEM_BYTES);

    int blocks = (E + EPB - 1) / EPB;
    tpc_edge_kernel<<<blocks, TPB, SMEM_BYTES>>>(
        scalar, vec, elen, eidx,
        sw1, sb1, sw2, sb2, vw1, vb1, vw2, vb2,
        (float*)d_out, E, nscal);
}